// round 8
// baseline (speedup 1.0000x reference)
#include <cuda_runtime.h>
#include <cuda_fp16.h>
#include <cuda_bf16.h>
#include <cstdint>

// Synapse_66400194396810: out[m,n] = tanh( w2 . tanh( w1 @ (A[m,n], pre[n], post[m]) + b1 ) + b2 )
// M = N = 4096, Nh = 8.
// R8: decouple DRAM latency from warps. R3-R7 swept instrs/MUFU/occ/ILP; dur pinned ~40us,
//     no pipe >37% -> per-thread LDG scoreboard coupling is the suspected wall.
//     One cp.async.bulk (16KB row of A) -> SMEM per block, mbarrier wait, compute from LDS.
//     pre-LDGs overlap the TMA. Math = R6 (half2 inner tanh, fp32 final).

#define NH 8
#define COLS 4096            // fixed problem shape
#define TILE_BYTES (COLS * 4)

// Half2-broadcast weight banks: [0..7]=w10, [8..15]=w11, [16..23]=w12, [24..31]=b1, [32..39]=w2, [40]=b2
__constant__ unsigned CWH[48];

__device__ __forceinline__ float htanh(float x) {
    float y;
    asm("tanh.approx.f32 %0, %1;" : "=f"(y) : "f"(x));
    return y;
}
__device__ __forceinline__ __half2 htanh2(__half2 x) {
    unsigned yi;
    asm("tanh.approx.f16x2 %0, %1;" : "=r"(yi) : "r"(*(unsigned*)&x));
    return *(__half2*)&yi;
}
__device__ __forceinline__ __half2 cwh2(int i) {
    unsigned v = CWH[i];
    return *(__half2*)&v;
}
__device__ __forceinline__ uint32_t smem_u32(const void* p) {
    uint32_t a;
    asm("{ .reg .u64 t; cvta.to.shared.u64 t, %1; cvt.u32.u64 %0, t; }" : "=r"(a) : "l"(p));
    return a;
}

// One-time fp32 -> half2-broadcast weight conversion, via the constant bank's global alias.
__global__ void pack_weights(const float* __restrict__ w1, const float* __restrict__ b1,
                             const float* __restrict__ w2, const float* __restrict__ b2,
                             unsigned* __restrict__ cwh) {
    const int i = threadIdx.x;
    if (i < NH) {
        __half2 h;
        h = __half2half2(__float2half_rn(w1[i * 3 + 0])); cwh[i]      = *(unsigned*)&h;
        h = __half2half2(__float2half_rn(w1[i * 3 + 1])); cwh[8 + i]  = *(unsigned*)&h;
        h = __half2half2(__float2half_rn(w1[i * 3 + 2])); cwh[16 + i] = *(unsigned*)&h;
        h = __half2half2(__float2half_rn(b1[i]));         cwh[24 + i] = *(unsigned*)&h;
        h = __half2half2(__float2half_rn(w2[i]));         cwh[32 + i] = *(unsigned*)&h;
        if (i == 0) {
            h = __half2half2(__float2half_rn(b2[0]));     cwh[40]     = *(unsigned*)&h;
        }
    }
}

__global__ void __launch_bounds__(256) synapse_kernel(
    const float* __restrict__ A,
    const float* __restrict__ pre,
    const float* __restrict__ post,
    float* __restrict__ out)
{
    __shared__ __align__(128) float sA[COLS];     // 16 KB: one full row of A
    __shared__ __align__(8)  uint64_t mbar;

    const int tid = threadIdx.x;
    const int row = blockIdx.x;
    const long long base = (long long)row * COLS;

    // --- Init mbarrier, then kick the bulk copy of this row (single async op). ---
    const uint32_t mb = smem_u32(&mbar);
    if (tid == 0) {
        asm volatile("mbarrier.init.shared.b64 [%0], %1;" :: "r"(mb), "r"(1) : "memory");
    }
    __syncthreads();
    if (tid == 0) {
        asm volatile("mbarrier.arrive.expect_tx.shared.b64 _, [%0], %1;"
                     :: "r"(mb), "r"((uint32_t)TILE_BYTES) : "memory");
        asm volatile("cp.async.bulk.shared::cluster.global.mbarrier::complete_tx::bytes "
                     "[%0], [%1], %2, [%3];"
                     :: "r"(smem_u32(sA)), "l"(A + base), "r"((uint32_t)TILE_BYTES), "r"(mb)
                     : "memory");
    }

    // --- Overlap with the TMA: load pre (L2-hot) and build row constants. ---
    __half2 p2lo[4], p2hi[4];
#pragma unroll
    for (int j = 0; j < 4; j++) {
        const float4 p4 = *reinterpret_cast<const float4*>(pre + (j * 256 + tid) * 4);
        p2lo[j] = __floats2half2_rn(p4.x, p4.y);
        p2hi[j] = __floats2half2_rn(p4.z, p4.w);
    }
    const __half2 pm2 = __float2half2_rn(post[row]);
    __half2 ch[NH];
#pragma unroll
    for (int h = 0; h < NH; h++) ch[h] = __hfma2(cwh2(16 + h), pm2, cwh2(24 + h));

    // --- Wait for the row of A (acquire: TMA smem writes visible after this). ---
    {
        uint32_t done;
        asm volatile(
            "{\n\t.reg .pred p;\n\t"
            "mbarrier.try_wait.parity.acquire.cta.shared::cta.b64 p, [%1], %2;\n\t"
            "selp.b32 %0, 1, 0, p;\n\t}"
            : "=r"(done) : "r"(mb), "r"(0u) : "memory");
        if (!done) {
            asm volatile(
                "{\n\t.reg .pred P1;\n\t"
                "W%=:\n\t"
                "mbarrier.try_wait.parity.acquire.cta.shared::cta.b64 P1, [%0], %1, 0x989680;\n\t"
                "@P1 bra.uni D%=;\n\t"
                "bra.uni W%=;\n\t"
                "D%=:\n\t}"
                :: "r"(mb), "r"(0u) : "memory");
        }
    }

    // --- Compute 16 elems/thread from SMEM (conflict-free float4 pattern). ---
    const float4* sA4 = reinterpret_cast<const float4*>(sA);
#pragma unroll
    for (int j = 0; j < 4; j++) {
        const float4 a4 = sA4[j * 256 + tid];
        const __half2 a2lo = __floats2half2_rn(a4.x, a4.y);
        const __half2 a2hi = __floats2half2_rn(a4.z, a4.w);

        __half2 acc_lo = cwh2(40);
        __half2 acc_hi = cwh2(40);
#pragma unroll
        for (int h = 0; h < NH; h++) {
            const __half2 w0 = cwh2(h), w1h = cwh2(8 + h), w2h = cwh2(32 + h);
            __half2 zlo = __hfma2(w0, a2lo, __hfma2(w1h, p2lo[j], ch[h]));
            __half2 zhi = __hfma2(w0, a2hi, __hfma2(w1h, p2hi[j], ch[h]));
            acc_lo = __hfma2(w2h, htanh2(zlo), acc_lo);
            acc_hi = __hfma2(w2h, htanh2(zhi), acc_hi);
        }
        const float2 flo = __half22float2(acc_lo);
        const float2 fhi = __half22float2(acc_hi);
        float4 o;
        o.x = htanh(flo.x);
        o.y = htanh(flo.y);
        o.z = htanh(fhi.x);
        o.w = htanh(fhi.y);
        *reinterpret_cast<float4*>(out + base + (j * 256 + tid) * 4) = o;
    }
}

extern "C" void kernel_launch(void* const* d_in, const int* in_sizes, int n_in,
                              void* d_out, int out_size) {
    const float* A    = (const float*)d_in[0];
    const float* pre  = (const float*)d_in[1];
    const float* post = (const float*)d_in[2];
    const float* w1   = (const float*)d_in[3];
    const float* b1   = (const float*)d_in[4];
    const float* w2   = (const float*)d_in[5];
    const float* b2   = (const float*)d_in[6];
    float* out = (float*)d_out;

    void* cwh_alias = nullptr;
    cudaGetSymbolAddress(&cwh_alias, CWH);

    pack_weights<<<1, 32>>>(w1, b1, w2, b2, (unsigned*)cwh_alias);

    const int M = out_size / COLS;   // 4096 rows, one block per row
    synapse_kernel<<<M, 256>>>(A, pre, post, out);
}